// round 16
// baseline (speedup 1.0000x reference)
#include <cuda_runtime.h>
#include <cuda_fp16.h>
#include <math.h>
#include <cstdint>

// Problem constants (fixed by the dataset)
#define NN 50000
#define NE 600000
#define C  128

#define SB 256
#define NB ((NN + SB - 1) / SB)   // 196 scan blocks

// ---------------- scratch (device globals: allocation-free rule) -------------
__device__ __align__(16) int   g_deg[NN];
__device__ __align__(16) int   g_off[NN + 1];
__device__ __align__(16) int   g_cur[NN];
__device__ __align__(16) int   g_bucket[NE];
// fp16 B tiles: [s(3)][kb(8)][n(128)][k(64)]; root stored at s=0, kb=6,7
__device__ __align__(16) __half g_B2[3 * 8 * 128 * 64];
// decoupled-lookback scan state (reset every run by k_zero_deg)
__device__ __align__(16) int   g_flag[NB];   // 0=none 1=aggregate 2=inclusive
__device__ __align__(16) int   g_aggI[NB];
__device__ __align__(16) int   g_incI[NB];
__device__ float g_logtot;
__device__ int   g_done;
__device__ float g_ref;
__device__ int   g_is64;

// ---------------- phase 0+1: dtype autodetect + zero state ----------------
__global__ void k_zero_deg(const int* __restrict__ ei32) {
    int i = blockIdx.x * blockDim.x + threadIdx.x;
    if (i < NN) g_deg[i] = 0;
    if (i < NB) g_flag[i] = 0;
    if (i == 0) {
        g_logtot = 0.f;
        g_done = 0;
        int odd_or = 0;
        for (int q = 0; q < 128; q++) odd_or |= ei32[2 * q + 1];
        g_is64 = (odd_or == 0) ? 1 : 0;
    }
}

__device__ __forceinline__ int load_edge(const void* ei, int idx) {
    int v;
    if (g_is64) v = (int)((const long long*)ei)[idx];
    else        v = ((const int*)ei)[idx];
    return min(max(v, 0), NN - 1);
}

__global__ void k_count(const void* __restrict__ ei) {
    int i = blockIdx.x * blockDim.x + threadIdx.x;
    if (i < NE) {
        int dst = load_edge(ei, NE + i);
        atomicAdd(&g_deg[dst], 1);
    }
}

// ---------------- fused scan: decoupled lookback (warp-parallel) ------------
__global__ void __launch_bounds__(SB)
k_scanfused() {
    __shared__ int   ps[SB];
    __shared__ float ls[SB];
    __shared__ int   sBase;
    const int t = threadIdx.x;
    const int bid = blockIdx.x;
    const int node = bid * SB + t;
    const int d = (node < NN) ? g_deg[node] : 0;

    ps[t] = d;
    ls[t] = (node < NN) ? log1pf((float)d + 1.0f) : 0.f;
    __syncthreads();
    for (int off = 1; off < SB; off <<= 1) {
        int a = 0;
        if (t >= off) a = ps[t - off];
        __syncthreads();
        if (t >= off) ps[t] += a;
        __syncthreads();
    }
    for (int off = SB / 2; off > 0; off >>= 1) {
        if (t < off) ls[t] += ls[t + off];
        __syncthreads();
    }
    const int total = ps[SB - 1];

    if (t == 0) {
        if (bid == 0) {
            g_incI[0] = total;
            __threadfence();
            atomicExch(&g_flag[0], 2);
            sBase = 0;
        } else {
            g_aggI[bid] = total;
            __threadfence();
            atomicExch(&g_flag[bid], 1);
        }
    }
    __syncwarp(0xffffffffu);

    if (t < 32 && bid > 0) {
        const int lane = t;
        int base = 0;
        int p = bid - 1;
        while (true) {
            int idx = p - lane;
            int f = (idx >= 0) ? atomicAdd(&g_flag[idx], 0) : 2;
            while (__any_sync(0xffffffffu, f == 0)) {
                if (f == 0) f = atomicAdd(&g_flag[idx], 0);
            }
            __threadfence();
            int v = 0;
            if (idx >= 0) v = (f == 2) ? g_incI[idx] : g_aggI[idx];
            unsigned incmask = __ballot_sync(0xffffffffu, f == 2);
            int firstinc = __ffs(incmask) - 1;
            int contrib = incmask ? ((lane <= firstinc) ? v : 0) : v;
#pragma unroll
            for (int o = 16; o > 0; o >>= 1)
                contrib += __shfl_down_sync(0xffffffffu, contrib, o);
            contrib = __shfl_sync(0xffffffffu, contrib, 0);
            base += contrib;
            if (incmask) break;
            p -= 32;
        }
        if (lane == 0) {
            g_incI[bid] = base + total;
            __threadfence();
            atomicExch(&g_flag[bid], 2);
            sBase = base;
        }
    }
    if (t == 0) {
        atomicAdd(&g_logtot, ls[0]);
        __threadfence();
        int old = atomicAdd(&g_done, 1);
        if (old == NB - 1) g_ref = fmaxf(g_logtot / (float)NN, 1.0f);
    }
    __syncthreads();
    const int base = sBase;
    if (bid == NB - 1 && t == 0) g_off[NN] = base + total;
    if (node < NN) {
        int off = base + ps[t] - d;
        g_off[node] = off;
        g_cur[node] = off;
    }
}

__global__ void k_scatter(const void* __restrict__ ei) {
    int i = blockIdx.x * blockDim.x + threadIdx.x;
    if (i < NE) {
        int src = load_edge(ei, i);
        int dst = load_edge(ei, NE + i);
        int pos = atomicAdd(&g_cur[dst], 1);
        if (pos >= 0 && pos < NE) g_bucket[pos] = src;
    }
}

// ---------------- phase 3a: build fp16 B tiles -------------------------------
__global__ void k_buildB(const float* __restrict__ Wmsg,
                         const float* __restrict__ Wroot) {
    int idx = blockIdx.x * blockDim.x + threadIdx.x;
    if (idx < 3 * 8 * 8192) {
        int s   = idx / 65536;
        int rem = idx - s * 65536;
        int kb  = rem >> 13;
        int r2  = rem & 8191;
        int n   = r2 >> 6;
        int k   = r2 & 63;
        float v = 0.f;
        if (kb < 6) {
            int kk  = kb * 64 + k;
            int seg = kk >> 7;
            int col = kk & 127;
            int j   = seg * 3 + s;
            v = Wmsg[(size_t)n * 1152 + j * 128 + col];
        } else if (s == 0) {
            int col = (kb - 6) * 64 + k;
            v = Wroot[(size_t)n * 128 + col];
        }
        g_B2[idx] = __float2half_rn(v);
    }
}

// ---------------- phase 3b: FUSED agg + M128 mma.sync GEMM ------------------
// CTA owns 128 nodes: phase A gathers edges (warp-per-node) and writes the
// fp16 A panel [sum | mean | max | x] directly to SMEM (no global round-trip),
// phase B runs the double-buffered 20-tile B loop with fp32 scaler merges.
#define NT 512
#define LDT 72
#define ABLK_B (128 * LDT * 2)            // 18432 bytes per A block
#define BTILE_B (128 * LDT * 2)           // 18432 bytes per B buffer
#define SM_BIAS 0
#define SM_AMP  512
#define SM_ATT  1024
#define SM_A    1536
#define SM_B0   (SM_A + 8 * ABLK_B)       // 148992
#define SM_B1   (SM_B0 + BTILE_B)         // 167424
#define SM_TOTAL (SM_B1 + BTILE_B)        // 185856

__device__ __forceinline__ void mma16816(float* c, const uint32_t* a, const uint32_t* b) {
    asm volatile(
        "mma.sync.aligned.m16n8k16.row.col.f32.f16.f16.f32 "
        "{%0,%1,%2,%3}, {%4,%5,%6,%7}, {%8,%9}, {%0,%1,%2,%3};"
        : "+f"(c[0]), "+f"(c[1]), "+f"(c[2]), "+f"(c[3])
        : "r"(a[0]), "r"(a[1]), "r"(a[2]), "r"(a[3]), "r"(b[0]), "r"(b[1]));
}

__device__ __forceinline__ void ldsm4(uint32_t* r, uint32_t addr) {
    asm volatile("ldmatrix.sync.aligned.m8n8.x4.shared.b16 {%0,%1,%2,%3}, [%4];"
                 : "=r"(r[0]), "=r"(r[1]), "=r"(r[2]), "=r"(r[3]) : "r"(addr));
}

__device__ __forceinline__ void do_mma_block(float acc[2][4][4],
                                             uint32_t aA0, uint32_t aA1,
                                             uint32_t bA0, uint32_t bA1) {
#pragma unroll
    for (int ks = 0; ks < 4; ks++) {
        uint32_t a0[4], a1[4], b0[4], b1[4];
        ldsm4(a0, aA0 + ks * 32);
        ldsm4(a1, aA1 + ks * 32);
        ldsm4(b0, bA0 + ks * 32);
        ldsm4(b1, bA1 + ks * 32);
        mma16816(acc[0][0], a0, &b0[0]);
        mma16816(acc[0][1], a0, &b0[2]);
        mma16816(acc[0][2], a0, &b1[0]);
        mma16816(acc[0][3], a0, &b1[2]);
        mma16816(acc[1][0], a1, &b0[0]);
        mma16816(acc[1][1], a1, &b0[2]);
        mma16816(acc[1][2], a1, &b1[0]);
        mma16816(acc[1][3], a1, &b1[2]);
    }
}

// async-copy one B tile [128][64] (linear) into padded SMEM buffer (512 thr)
__device__ __forceinline__ void issue_btile(uint32_t sdst, const __half* src, int tid) {
#pragma unroll
    for (int it = 0; it < 2; it++) {
        int idx = tid + it * NT;
        int row = idx >> 3;
        int ch  = idx & 7;
        asm volatile("cp.async.cg.shared.global [%0], [%1], 16;"
                     :: "r"(sdst + (uint32_t)((row * LDT + ch * 8) * 2)),
                        "l"(src + row * 64 + ch * 8));
    }
    asm volatile("cp.async.commit_group;" ::: "memory");
}

// linear tile t (0..19) -> offset in g_B2 (in halfs)
__device__ __forceinline__ size_t tile_off(int t) {
    if (t < 18) return (size_t)((t / 6) * 8 + (t % 6)) * 8192;
    return (size_t)(t - 12) * 8192;   // t=18 -> kb6, t=19 -> kb7 (s=0 region)
}

// store one row's 4 channels (c0 = lid*4) into A block-pair bp, scaled
__device__ __forceinline__ void store_row(__half* sA, int bp, int r, int lid,
                                          float4 v, float coef) {
    int blk = bp * 2 + (lid >> 4);
    int col = (lid & 15) * 4;
    __half* dst = sA + blk * (128 * LDT) + r * LDT + col;
    __half2 h0 = __float22half2_rn(make_float2(v.x * coef, v.y * coef));
    __half2 h1 = __float22half2_rn(make_float2(v.z * coef, v.w * coef));
    *(__half2*)dst = h0;
    *(__half2*)(dst + 2) = h1;
}

__global__ void __launch_bounds__(NT, 1)
k_gemm_fused(const float* __restrict__ x,
             const float* __restrict__ bmsg,
             const float* __restrict__ broot,
             float* __restrict__ out) {
    extern __shared__ char smem[];
    float*  sBias = (float*)(smem + SM_BIAS);
    float*  sAmp  = (float*)(smem + SM_AMP);
    float*  sAtt  = (float*)(smem + SM_ATT);
    __half* sA = (__half*)(smem + SM_A);

    const int tid = threadIdx.x;
    const int wid = tid >> 5;
    const int lid = tid & 31;
    const int m0 = blockIdx.x * 128;

    uint32_t sBaddr[2];
    sBaddr[0] = (uint32_t)__cvta_generic_to_shared(smem + SM_B0);
    sBaddr[1] = (uint32_t)__cvta_generic_to_shared(smem + SM_B1);

    // kick off tile 0 copy immediately (overlaps the gather)
    issue_btile(sBaddr[0], g_B2 + tile_off(0), tid);

    if (tid < 128) sBias[tid] = bmsg[tid] + broot[tid];
    const float rf = g_ref;

    // ---- phase A: warp-per-node gather + fp16 A-panel staging ----
    const int c0 = lid * 4;
#pragma unroll 1
    for (int k = 0; k < 8; k++) {
        const int r = wid * 8 + k;          // local row 0..127
        const int node = m0 + r;
        float4 s  = make_float4(0.f, 0.f, 0.f, 0.f);
        float4 mx = make_float4(-1e30f, -1e30f, -1e30f, -1e30f);
        float4 xv = make_float4(0.f, 0.f, 0.f, 0.f);
        int deg = 0;
        if (node < NN) {
            int beg = g_off[node], end = g_off[node + 1];
            deg = end - beg;
            int e = beg;
            for (; e + 4 <= end; e += 4) {
                int i0 = g_bucket[e];
                int i1 = g_bucket[e + 1];
                int i2 = g_bucket[e + 2];
                int i3 = g_bucket[e + 3];
                float4 v0 = *(const float4*)&x[(size_t)i0 * C + c0];
                float4 v1 = *(const float4*)&x[(size_t)i1 * C + c0];
                float4 v2 = *(const float4*)&x[(size_t)i2 * C + c0];
                float4 v3 = *(const float4*)&x[(size_t)i3 * C + c0];
                s.x += (v0.x + v1.x) + (v2.x + v3.x);
                s.y += (v0.y + v1.y) + (v2.y + v3.y);
                s.z += (v0.z + v1.z) + (v2.z + v3.z);
                s.w += (v0.w + v1.w) + (v2.w + v3.w);
                mx.x = fmaxf(mx.x, fmaxf(fmaxf(v0.x, v1.x), fmaxf(v2.x, v3.x)));
                mx.y = fmaxf(mx.y, fmaxf(fmaxf(v0.y, v1.y), fmaxf(v2.y, v3.y)));
                mx.z = fmaxf(mx.z, fmaxf(fmaxf(v0.z, v1.z), fmaxf(v2.z, v3.z)));
                mx.w = fmaxf(mx.w, fmaxf(fmaxf(v0.w, v1.w), fmaxf(v2.w, v3.w)));
            }
            for (; e < end; e++) {
                int i0 = g_bucket[e];
                float4 v0 = *(const float4*)&x[(size_t)i0 * C + c0];
                s.x += v0.x; s.y += v0.y; s.z += v0.z; s.w += v0.w;
                mx.x = fmaxf(mx.x, v0.x); mx.y = fmaxf(mx.y, v0.y);
                mx.z = fmaxf(mx.z, v0.z); mx.w = fmaxf(mx.w, v0.w);
            }
            xv = *(const float4*)&x[(size_t)node * C + c0];
        }
        if (deg <= 0) mx = make_float4(0.f, 0.f, 0.f, 0.f);
        float minv = 1.0f / fmaxf((float)deg, 1.0f);

        store_row(sA, 0, r, lid, s,  1.f);
        store_row(sA, 1, r, lid, s,  minv);
        store_row(sA, 2, r, lid, mx, 1.f);
        store_row(sA, 3, r, lid, xv, 1.f);
        if (lid == 0) {
            if (node < NN) {
                float dt = log1pf((float)deg + 1.0f);
                sAmp[r] = dt / rf;
                sAtt[r] = rf / fmaxf(dt, 1e-6f);
            } else {
                sAmp[r] = 0.f;
                sAtt[r] = 0.f;
            }
        }
    }

    // warp tiling: 4 m-warps x 4 n-warps; warp tile 32(M) x 32(N)
    const int mw = wid >> 2;
    const int nw = wid & 3;
    const int g  = lid >> 2;
    const int tg = lid & 3;

    const int arow0 = mw * 32 + (lid & 7) + (lid & 8);
    const int acol  = ((lid & 16) >> 1);
    uint32_t aA0 = (uint32_t)__cvta_generic_to_shared(sA + (arow0 + 0)  * LDT + acol);
    uint32_t aA1 = (uint32_t)__cvta_generic_to_shared(sA + (arow0 + 16) * LDT + acol);

    const uint32_t bfo0 = (uint32_t)(((nw * 32 + ((lid & 16) >> 1) + (lid & 7)) * LDT
                                      + (lid & 8)) * 2);
    const uint32_t bfo1 = bfo0 + (uint32_t)(16 * LDT * 2);

    float accF[2][4][4], accW[2][4][4];
#pragma unroll
    for (int i = 0; i < 2; i++)
#pragma unroll
        for (int j = 0; j < 4; j++)
#pragma unroll
            for (int q = 0; q < 4; q++) { accF[i][j][q] = 0.f; accW[i][j][q] = 0.f; }

    // ---- phase B: pipelined 20-tile loop ----
    for (int t = 0; t < 20; t++) {
        asm volatile("cp.async.wait_group 0;" ::: "memory");
        __syncthreads();
        if (t < 19)
            issue_btile(sBaddr[(t + 1) & 1], g_B2 + tile_off(t + 1), tid);

        const uint32_t bb = sBaddr[t & 1];
        const int ablk = (t < 18) ? (t % 6) : (t - 12);
        const uint32_t ao = (uint32_t)(ablk * ABLK_B);
        if (t < 18)
            do_mma_block(accW, aA0 + ao, aA1 + ao, bb + bfo0, bb + bfo1);
        else
            do_mma_block(accF, aA0 + ao, aA1 + ao, bb + bfo0, bb + bfo1);

        // merge at s-group boundaries (register-only)
        if (t == 5 || t == 11 || t == 17) {
            const int s = t / 6;
            if (s == 0) {
#pragma unroll
                for (int i = 0; i < 2; i++)
#pragma unroll
                    for (int j = 0; j < 4; j++)
#pragma unroll
                        for (int q = 0; q < 4; q++) {
                            accF[i][j][q] += accW[i][j][q];
                            accW[i][j][q] = 0.f;
                        }
            } else {
                const float* carr = (s == 1) ? sAmp : sAtt;
#pragma unroll
                for (int i = 0; i < 2; i++) {
                    int r0 = mw * 32 + i * 16 + g;
                    float cf0 = carr[r0];
                    float cf1 = carr[r0 + 8];
#pragma unroll
                    for (int j = 0; j < 4; j++) {
                        accF[i][j][0] += cf0 * accW[i][j][0];
                        accF[i][j][1] += cf0 * accW[i][j][1];
                        accF[i][j][2] += cf1 * accW[i][j][2];
                        accF[i][j][3] += cf1 * accW[i][j][3];
                        accW[i][j][0] = 0.f; accW[i][j][1] = 0.f;
                        accW[i][j][2] = 0.f; accW[i][j][3] = 0.f;
                    }
                }
            }
        }
    }

    // ---- epilogue ----
#pragma unroll
    for (int i = 0; i < 2; i++) {
#pragma unroll
        for (int j = 0; j < 4; j++) {
            int col  = nw * 32 + j * 8 + 2 * tg;
            int row0 = m0 + mw * 32 + i * 16 + g;
            int row1 = row0 + 8;
            float bi0 = sBias[col], bi1 = sBias[col + 1];
            if (row0 < NN) {
                float2 v = make_float2(accF[i][j][0] + bi0, accF[i][j][1] + bi1);
                *(float2*)&out[(size_t)row0 * C + col] = v;
            }
            if (row1 < NN) {
                float2 v = make_float2(accF[i][j][2] + bi0, accF[i][j][3] + bi1);
                *(float2*)&out[(size_t)row1 * C + col] = v;
            }
        }
    }
}

// ---------------- launch ----------------
extern "C" void kernel_launch(void* const* d_in, const int* in_sizes, int n_in,
                              void* d_out, int out_size) {
    const float* x     = (const float*)d_in[0];
    const void*  ei    = d_in[1];
    const float* Wmsg  = (const float*)d_in[2];
    const float* bmsg  = (const float*)d_in[3];
    const float* Wroot = (const float*)d_in[4];
    const float* broot = (const float*)d_in[5];
    float*       out   = (float*)d_out;

    cudaFuncSetAttribute(k_gemm_fused, cudaFuncAttributeMaxDynamicSharedMemorySize,
                         SM_TOTAL);

    k_zero_deg<<<(NN + 255) / 256, 256>>>((const int*)ei);
    k_count<<<(NE + 255) / 256, 256>>>(ei);
    k_scanfused<<<NB, SB>>>();
    k_scatter<<<(NE + 255) / 256, 256>>>(ei);
    k_buildB<<<(3 * 8 * 8192 + 255) / 256, 256>>>(Wmsg, Wroot);
    k_gemm_fused<<<(NN + 127) / 128, NT, SM_TOTAL>>>(x, bmsg, broot, out);
}

// round 17
// speedup vs baseline: 1.0779x; 1.0779x over previous
#include <cuda_runtime.h>
#include <cuda_fp16.h>
#include <math.h>
#include <cstdint>

// Problem constants (fixed by the dataset)
#define NN 50000
#define NE 600000
#define C  128

#define SB 256
#define NB ((NN + SB - 1) / SB)   // 196 scan blocks

// ---------------- scratch (device globals: allocation-free rule) -------------
__device__ __align__(16) __half g_xh[(size_t)NN * C];   // fp16 x
__device__ __align__(16) __half g_Ash[(size_t)NN * C];  // fp16 sum
__device__ __align__(16) __half g_Amh[(size_t)NN * C];  // fp16 max
__device__ __align__(16) int   g_deg[NN];
__device__ __align__(16) int   g_off[NN + 1];
__device__ __align__(16) int   g_cur[NN];
__device__ __align__(16) int   g_bucket[NE];
__device__ __align__(16) float g_amp[NN];
__device__ __align__(16) float g_att[NN];
__device__ __align__(16) float g_minv[NN];
// fp16 B tiles: [s(3)][kb(8)][n(128)][k(64)]; root stored at s=0, kb=6,7
__device__ __align__(16) __half g_B2[3 * 8 * 128 * 64];
// decoupled-lookback scan state (reset every run by k_zero_deg)
__device__ __align__(16) int   g_flag[NB];
__device__ __align__(16) int   g_aggI[NB];
__device__ __align__(16) int   g_incI[NB];
__device__ float g_logtot;
__device__ int   g_done;
__device__ float g_ref;
__device__ int   g_is64;

// ---------------- phase 0+1: dtype autodetect + zero state ----------------
__global__ void k_zero_deg(const int* __restrict__ ei32) {
    int i = blockIdx.x * blockDim.x + threadIdx.x;
    if (i < NN) g_deg[i] = 0;
    if (i < NB) g_flag[i] = 0;
    if (i == 0) {
        g_logtot = 0.f;
        g_done = 0;
        int odd_or = 0;
        for (int q = 0; q < 128; q++) odd_or |= ei32[2 * q + 1];
        g_is64 = (odd_or == 0) ? 1 : 0;
    }
}

// x -> fp16 (one-time)
__global__ void k_convx(const float* __restrict__ x) {
    int i = blockIdx.x * blockDim.x + threadIdx.x;
    if (i < NN * C / 4) {
        float4 v = ((const float4*)x)[i];
        __half2 h0 = __floats2half2_rn(v.x, v.y);
        __half2 h1 = __floats2half2_rn(v.z, v.w);
        ((__half2*)g_xh)[2 * i]     = h0;
        ((__half2*)g_xh)[2 * i + 1] = h1;
    }
}

__device__ __forceinline__ int load_edge(const void* ei, int idx) {
    int v;
    if (g_is64) v = (int)((const long long*)ei)[idx];
    else        v = ((const int*)ei)[idx];
    return min(max(v, 0), NN - 1);
}

__global__ void k_count(const void* __restrict__ ei) {
    int i = blockIdx.x * blockDim.x + threadIdx.x;
    if (i < NE) {
        int dst = load_edge(ei, NE + i);
        atomicAdd(&g_deg[dst], 1);
    }
}

// ---------------- fused scan: decoupled lookback (warp-parallel) ------------
__global__ void __launch_bounds__(SB)
k_scanfused() {
    __shared__ int   ps[SB];
    __shared__ float ls[SB];
    __shared__ int   sBase;
    const int t = threadIdx.x;
    const int bid = blockIdx.x;
    const int node = bid * SB + t;
    const int d = (node < NN) ? g_deg[node] : 0;

    ps[t] = d;
    ls[t] = (node < NN) ? log1pf((float)d + 1.0f) : 0.f;
    __syncthreads();
    for (int off = 1; off < SB; off <<= 1) {
        int a = 0;
        if (t >= off) a = ps[t - off];
        __syncthreads();
        if (t >= off) ps[t] += a;
        __syncthreads();
    }
    for (int off = SB / 2; off > 0; off >>= 1) {
        if (t < off) ls[t] += ls[t + off];
        __syncthreads();
    }
    const int total = ps[SB - 1];

    if (t == 0) {
        if (bid == 0) {
            g_incI[0] = total;
            __threadfence();
            atomicExch(&g_flag[0], 2);
            sBase = 0;
        } else {
            g_aggI[bid] = total;
            __threadfence();
            atomicExch(&g_flag[bid], 1);
        }
    }
    __syncwarp(0xffffffffu);

    if (t < 32 && bid > 0) {
        const int lane = t;
        int base = 0;
        int p = bid - 1;
        while (true) {
            int idx = p - lane;
            int f = (idx >= 0) ? atomicAdd(&g_flag[idx], 0) : 2;
            while (__any_sync(0xffffffffu, f == 0)) {
                if (f == 0) f = atomicAdd(&g_flag[idx], 0);
            }
            __threadfence();
            int v = 0;
            if (idx >= 0) v = (f == 2) ? g_incI[idx] : g_aggI[idx];
            unsigned incmask = __ballot_sync(0xffffffffu, f == 2);
            int firstinc = __ffs(incmask) - 1;
            int contrib = incmask ? ((lane <= firstinc) ? v : 0) : v;
#pragma unroll
            for (int o = 16; o > 0; o >>= 1)
                contrib += __shfl_down_sync(0xffffffffu, contrib, o);
            contrib = __shfl_sync(0xffffffffu, contrib, 0);
            base += contrib;
            if (incmask) break;
            p -= 32;
        }
        if (lane == 0) {
            g_incI[bid] = base + total;
            __threadfence();
            atomicExch(&g_flag[bid], 2);
            sBase = base;
        }
    }
    if (t == 0) {
        atomicAdd(&g_logtot, ls[0]);
        __threadfence();
        int old = atomicAdd(&g_done, 1);
        if (old == NB - 1) g_ref = fmaxf(g_logtot / (float)NN, 1.0f);
    }
    __syncthreads();
    const int base = sBase;
    if (bid == NB - 1 && t == 0) g_off[NN] = base + total;
    if (node < NN) {
        int off = base + ps[t] - d;
        g_off[node] = off;
        g_cur[node] = off;
    }
}

__global__ void k_scatter(const void* __restrict__ ei) {
    int i = blockIdx.x * blockDim.x + threadIdx.x;
    if (i < NE) {
        int src = load_edge(ei, i);
        int dst = load_edge(ei, NE + i);
        int pos = atomicAdd(&g_cur[dst], 1);
        if (pos >= 0 && pos < NE) g_bucket[pos] = src;
    }
}

// ---------------- phase 2: warp-per-node gather-reduce (fp16 in/out) --------
__device__ __forceinline__ void acc2(float2& sf, float2& mf, uint32_t u) {
    float2 f = __half22float2(*(__half2*)&u);
    sf.x += f.x; sf.y += f.y;
    mf.x = fmaxf(mf.x, f.x); mf.y = fmaxf(mf.y, f.y);
}

__global__ void __launch_bounds__(256)
k_agg() {
    int wid = threadIdx.x >> 5;
    int lane = threadIdx.x & 31;
    int node = blockIdx.x * 8 + wid;
    if (node >= NN) return;
    int beg = g_off[node], end = g_off[node + 1];
    int deg = end - beg;
    int c0 = lane * 4;

    float2 s0 = make_float2(0.f, 0.f), s1 = make_float2(0.f, 0.f);
    float2 m0 = make_float2(-1e30f, -1e30f), m1 = make_float2(-1e30f, -1e30f);

    int e = beg;
    for (; e + 4 <= end; e += 4) {
        uint2 u0 = *(const uint2*)&g_xh[(size_t)g_bucket[e]     * C + c0];
        uint2 u1 = *(const uint2*)&g_xh[(size_t)g_bucket[e + 1] * C + c0];
        uint2 u2 = *(const uint2*)&g_xh[(size_t)g_bucket[e + 2] * C + c0];
        uint2 u3 = *(const uint2*)&g_xh[(size_t)g_bucket[e + 3] * C + c0];
        acc2(s0, m0, u0.x); acc2(s1, m1, u0.y);
        acc2(s0, m0, u1.x); acc2(s1, m1, u1.y);
        acc2(s0, m0, u2.x); acc2(s1, m1, u2.y);
        acc2(s0, m0, u3.x); acc2(s1, m1, u3.y);
    }
    for (; e < end; e++) {
        uint2 u0 = *(const uint2*)&g_xh[(size_t)g_bucket[e] * C + c0];
        acc2(s0, m0, u0.x); acc2(s1, m1, u0.y);
    }
    if (deg <= 0) {
        m0 = make_float2(0.f, 0.f);
        m1 = make_float2(0.f, 0.f);
    }
    __half2 hs0 = __floats2half2_rn(s0.x, s0.y);
    __half2 hs1 = __floats2half2_rn(s1.x, s1.y);
    __half2 hm0 = __floats2half2_rn(m0.x, m0.y);
    __half2 hm1 = __floats2half2_rn(m1.x, m1.y);
    *(__half2*)&g_Ash[(size_t)node * C + c0]     = hs0;
    *(__half2*)&g_Ash[(size_t)node * C + c0 + 2] = hs1;
    *(__half2*)&g_Amh[(size_t)node * C + c0]     = hm0;
    *(__half2*)&g_Amh[(size_t)node * C + c0 + 2] = hm1;
    if (lane == 0) {
        float dt = log1pf((float)deg + 1.0f);
        float rf = g_ref;
        g_amp[node]  = dt / rf;
        g_att[node]  = rf / fmaxf(dt, 1e-6f);
        g_minv[node] = 1.0f / fmaxf((float)deg, 1.0f);
    }
}

// ---------------- phase 3a: build fp16 B tiles -------------------------------
__global__ void k_buildB(const float* __restrict__ Wmsg,
                         const float* __restrict__ Wroot) {
    int idx = blockIdx.x * blockDim.x + threadIdx.x;
    if (idx < 3 * 8 * 8192) {
        int s   = idx / 65536;
        int rem = idx - s * 65536;
        int kb  = rem >> 13;
        int r2  = rem & 8191;
        int n   = r2 >> 6;
        int k   = r2 & 63;
        float v = 0.f;
        if (kb < 6) {
            int kk  = kb * 64 + k;
            int seg = kk >> 7;
            int col = kk & 127;
            int j   = seg * 3 + s;
            v = Wmsg[(size_t)n * 1152 + j * 128 + col];
        } else if (s == 0) {
            int col = (kb - 6) * 64 + k;
            v = Wroot[(size_t)n * 128 + col];
        }
        g_B2[idx] = __float2half_rn(v);
    }
}

// ---------------- phase 3b: staged-A mma.sync GEMM (fp16 sources) -----------
#define LDT 72
#define ABLK_B (64 * LDT * 2)             // 9216 bytes per A block
#define SM_BIAS 0
#define SM_A    512
#define SM_B    (SM_A + 8 * ABLK_B)       // 74240
#define SM_TOTAL (SM_B + 128 * LDT * 2)   // 92672

__device__ __forceinline__ void mma16816(float* c, const uint32_t* a, const uint32_t* b) {
    asm volatile(
        "mma.sync.aligned.m16n8k16.row.col.f32.f16.f16.f32 "
        "{%0,%1,%2,%3}, {%4,%5,%6,%7}, {%8,%9}, {%0,%1,%2,%3};"
        : "+f"(c[0]), "+f"(c[1]), "+f"(c[2]), "+f"(c[3])
        : "r"(a[0]), "r"(a[1]), "r"(a[2]), "r"(a[3]), "r"(b[0]), "r"(b[1]));
}

__device__ __forceinline__ void ldsm4(uint32_t* r, uint32_t addr) {
    asm volatile("ldmatrix.sync.aligned.m8n8.x4.shared.b16 {%0,%1,%2,%3}, [%4];"
                 : "=r"(r[0]), "=r"(r[1]), "=r"(r[2]), "=r"(r[3]) : "r"(addr));
}

__device__ __forceinline__ void do_mma_block(float acc[2][4][4],
                                             uint32_t aA0, uint32_t aA1,
                                             uint32_t bA0, uint32_t bA1) {
#pragma unroll
    for (int ks = 0; ks < 4; ks++) {
        uint32_t a0[4], a1[4], b0[4], b1[4];
        ldsm4(a0, aA0 + ks * 32);
        ldsm4(a1, aA1 + ks * 32);
        ldsm4(b0, bA0 + ks * 32);
        ldsm4(b1, bA1 + ks * 32);
        mma16816(acc[0][0], a0, &b0[0]);
        mma16816(acc[0][1], a0, &b0[2]);
        mma16816(acc[0][2], a0, &b1[0]);
        mma16816(acc[0][3], a0, &b1[2]);
        mma16816(acc[1][0], a1, &b0[0]);
        mma16816(acc[1][1], a1, &b0[2]);
        mma16816(acc[1][2], a1, &b1[0]);
        mma16816(acc[1][3], a1, &b1[2]);
    }
}

__device__ __forceinline__ void load_btile(__half* dst, const __half* src, int tid) {
#pragma unroll
    for (int it = 0; it < 4; it++) {
        int idx = tid + it * 256;
        int row = idx >> 3;
        int ch  = idx & 7;
        *(uint4*)&dst[row * LDT + ch * 8] = *(const uint4*)&src[row * 64 + ch * 8];
    }
}

__device__ __forceinline__ uint32_t scale_h2(uint32_t u, float s) {
    float2 f = __half22float2(*(__half2*)&u);
    __half2 r = __floats2half2_rn(f.x * s, f.y * s);
    return *(uint32_t*)&r;
}

__global__ void __launch_bounds__(256, 2)
k_gemm_mma(const float* __restrict__ bmsg,
           const float* __restrict__ broot,
           float* __restrict__ out) {
    extern __shared__ char smem[];
    float*  sBias = (float*)(smem + SM_BIAS);
    __half* sA = (__half*)(smem + SM_A);
    __half* sB = (__half*)(smem + SM_B);

    const int tid = threadIdx.x;
    const int wid = tid >> 5;
    const int lid = tid & 31;
    const int m0 = blockIdx.x * 64;

    if (tid < 128) sBias[tid] = bmsg[tid] + broot[tid];

    // ---- stage A panel: 8 blocks of 64 rows x 64 k-cols (fp16 sources) ----
    {
        const int r = tid >> 2;
        const int q = tid & 3;
        const int mc = min(m0 + r, NN - 1);
        const float minv = g_minv[mc];
#pragma unroll
        for (int bp = 0; bp < 4; bp++) {
            const __half* srcb = (bp < 2) ? g_Ash : ((bp == 2) ? g_Amh : g_xh);
#pragma unroll
            for (int h = 0; h < 2; h++) {
                int blk = bp * 2 + h;
                const __half* p = srcb + (size_t)mc * C + h * 64 + q * 16;
                __half* dst = sA + blk * (64 * LDT) + r * LDT + q * 16;
                uint4 v0 = *(const uint4*)p;
                uint4 v1 = *(const uint4*)(p + 8);
                if (bp == 1) {   // mean = sum * minv
                    v0.x = scale_h2(v0.x, minv); v0.y = scale_h2(v0.y, minv);
                    v0.z = scale_h2(v0.z, minv); v0.w = scale_h2(v0.w, minv);
                    v1.x = scale_h2(v1.x, minv); v1.y = scale_h2(v1.y, minv);
                    v1.z = scale_h2(v1.z, minv); v1.w = scale_h2(v1.w, minv);
                }
                *(uint4*)dst = v0;
                *(uint4*)(dst + 8) = v1;
            }
        }
    }

    const int mw = wid >> 2;
    const int nw = wid & 3;
    const int g  = lid >> 2;
    const int tg = lid & 3;

    const int arow0 = mw * 32 + (lid & 7) + (lid & 8);
    const int acol  = ((lid & 16) >> 1);
    uint32_t aA0 = (uint32_t)__cvta_generic_to_shared(sA + (arow0 + 0)  * LDT + acol);
    uint32_t aA1 = (uint32_t)__cvta_generic_to_shared(sA + (arow0 + 16) * LDT + acol);

    const int brow0 = nw * 32 + ((lid & 16) >> 1) + (lid & 7);
    const int bcol  = (lid & 8);
    uint32_t bA0 = (uint32_t)__cvta_generic_to_shared(sB + (brow0 + 0)  * LDT + bcol);
    uint32_t bA1 = (uint32_t)__cvta_generic_to_shared(sB + (brow0 + 16) * LDT + bcol);

    float accF[2][4][4];
#pragma unroll
    for (int i = 0; i < 2; i++)
#pragma unroll
        for (int j = 0; j < 4; j++)
#pragma unroll
            for (int q = 0; q < 4; q++) accF[i][j][q] = 0.f;

    __syncthreads();

    // ---- 3 scaler groups over shared A panel ----
    for (int s = 0; s < 3; s++) {
        float accW[2][4][4];
#pragma unroll
        for (int i = 0; i < 2; i++)
#pragma unroll
            for (int j = 0; j < 4; j++)
#pragma unroll
                for (int q = 0; q < 4; q++) accW[i][j][q] = 0.f;

        for (int kb = 0; kb < 6; kb++) {
            load_btile(sB, g_B2 + (size_t)(s * 8 + kb) * 8192, tid);
            __syncthreads();
            uint32_t ab = (uint32_t)(kb * ABLK_B);
            do_mma_block(accW, aA0 + ab, aA1 + ab, bA0, bA1);
            __syncthreads();
        }

        if (s == 0) {
#pragma unroll
            for (int i = 0; i < 2; i++)
#pragma unroll
                for (int j = 0; j < 4; j++)
#pragma unroll
                    for (int q = 0; q < 4; q++) accF[i][j][q] += accW[i][j][q];
        } else {
            const float* carr = (s == 1) ? g_amp : g_att;
#pragma unroll
            for (int i = 0; i < 2; i++) {
                int r0 = min(m0 + mw * 32 + i * 16 + g,     NN - 1);
                int r1 = min(m0 + mw * 32 + i * 16 + g + 8, NN - 1);
                float cf0 = carr[r0];
                float cf1 = carr[r1];
#pragma unroll
                for (int j = 0; j < 4; j++) {
                    accF[i][j][0] += cf0 * accW[i][j][0];
                    accF[i][j][1] += cf0 * accW[i][j][1];
                    accF[i][j][2] += cf1 * accW[i][j][2];
                    accF[i][j][3] += cf1 * accW[i][j][3];
                }
            }
        }
    }

    // ---- root blocks (x @ Wroot^T): kb 6,7 at s=0 region ----
    for (int kb = 6; kb < 8; kb++) {
        load_btile(sB, g_B2 + (size_t)kb * 8192, tid);
        __syncthreads();
        uint32_t ab = (uint32_t)(kb * ABLK_B);
        do_mma_block(accF, aA0 + ab, aA1 + ab, bA0, bA1);
        __syncthreads();
    }

    // ---- epilogue ----
#pragma unroll
    for (int i = 0; i < 2; i++) {
#pragma unroll
        for (int j = 0; j < 4; j++) {
            int col  = nw * 32 + j * 8 + 2 * tg;
            int row0 = m0 + mw * 32 + i * 16 + g;
            int row1 = row0 + 8;
            float bi0 = sBias[col], bi1 = sBias[col + 1];
            if (row0 < NN) {
                float2 v = make_float2(accF[i][j][0] + bi0, accF[i][j][1] + bi1);
                *(float2*)&out[(size_t)row0 * C + col] = v;
            }
            if (row1 < NN) {
                float2 v = make_float2(accF[i][j][2] + bi0, accF[i][j][3] + bi1);
                *(float2*)&out[(size_t)row1 * C + col] = v;
            }
        }
    }
}

// ---------------- launch ----------------
extern "C" void kernel_launch(void* const* d_in, const int* in_sizes, int n_in,
                              void* d_out, int out_size) {
    const float* x     = (const float*)d_in[0];
    const void*  ei    = d_in[1];
    const float* Wmsg  = (const float*)d_in[2];
    const float* bmsg  = (const float*)d_in[3];
    const float* Wroot = (const float*)d_in[4];
    const float* broot = (const float*)d_in[5];
    float*       out   = (float*)d_out;

    cudaFuncSetAttribute(k_gemm_mma, cudaFuncAttributeMaxDynamicSharedMemorySize,
                         SM_TOTAL);

    k_zero_deg<<<(NN + 255) / 256, 256>>>((const int*)ei);
    k_convx<<<(NN * C / 4 + 255) / 256, 256>>>(x);
    k_count<<<(NE + 255) / 256, 256>>>(ei);
    k_scanfused<<<NB, SB>>>();
    k_scatter<<<(NE + 255) / 256, 256>>>(ei);
    k_agg<<<(NN + 7) / 8, 256>>>();
    k_buildB<<<(3 * 8 * 8192 + 255) / 256, 256>>>(Wmsg, Wroot);
    k_gemm_mma<<<(NN + 63) / 64, 256, SM_TOTAL>>>(bmsg, broot, out);
}